// round 13
// baseline (speedup 1.0000x reference)
#include <cuda_runtime.h>

// GCN_12867722019091 — 2-layer GCN, N=50000, E=800000, HID=64, OUT=2.
// Split PDL chain (R7, 32.8us) + smem full-table gather for scat1 ONLY.
// R12 lesson: scat2's two-half-table smem variant double-reads the edge list
// and convoys at 1 block/SM -> revert scat2 to plain global gather.

constexpr int NN  = 50000;
constexpr int NE  = 800000;
constexpr int HID = 64;

__device__ int    g_deg[NN];
__device__ float  g_dinv[NN];
__device__ float  g_p[NN];      // x[n] * dinv[n]
__device__ float  g_s1[NN];     // layer-1 scalar scatter accumulator
__device__ float2 g_p2[NN];     // g[n,:] * dinv[n]
__device__ float2 g_acc[NN];    // layer-2 float2 scatter accumulator

__device__ __forceinline__ void pdl_wait() {
#if __CUDA_ARCH__ >= 900
    asm volatile("griddepcontrol.wait;" ::: "memory");
#endif
}
__device__ __forceinline__ void pdl_trigger() {
#if __CUDA_ARCH__ >= 900
    asm volatile("griddepcontrol.launch_dependents;" ::: "memory");
#endif
}

// ---- edge pass 1: in-degree count (1 edge/thread — proven config) ----
__global__ void __launch_bounds__(256) k_count(const int* __restrict__ col) {
    int i = blockIdx.x * blockDim.x + threadIdx.x;
    int c = (i < NE) ? col[i] : 0;               // prologue (independent)
    pdl_wait();                                   // prev replay's reset done
    pdl_trigger();
    if (i < NE) atomicAdd(&g_deg[c], 1);
}

// ---- node pass 1: dinv = rsqrt(deg+1); p = x*dinv ----
__global__ void __launch_bounds__(256) k_node1(const float* __restrict__ x) {
    int i = blockIdx.x * blockDim.x + threadIdx.x;
    float xv = (i < NN) ? x[i] : 0.f;             // prologue
    pdl_wait();                                   // g_deg ready
    pdl_trigger();
    if (i >= NN) return;
    float dinv = rsqrtf((float)(g_deg[i] + 1));
    g_dinv[i] = dinv;
    g_p[i]    = xv * dinv;
}

// ---- edge pass 2: s1[c] += p[r], gather from smem (full 195KB table) ----
__global__ void __launch_bounds__(1024) k_scat1(const int* __restrict__ row,
                                                const int* __restrict__ col) {
    extern __shared__ float sp[];                 // NN floats
    pdl_wait();                                   // g_p ready
    const int t  = threadIdx.x;
    const int nt = gridDim.x * 1024;
    // fill: whole p table into smem (coalesced; source is L2-resident)
    for (int i = t; i < NN; i += 1024) sp[i] = g_p[i];
    __syncthreads();
    pdl_trigger();
    for (int i = blockIdx.x * 1024 + t; i < NE; i += nt) {
        int r = row[i];
        int c = col[i];
        atomicAdd(&g_s1[c], sp[r]);
    }
}

// ---- node pass 2: s1 = dinv*(acc+p); h1 = relu(W1*s1+b1); p2 = (h1@W2)*dinv ----
__global__ void __launch_bounds__(256) k_node2(const float* __restrict__ W1,
                                               const float* __restrict__ b1,
                                               const float* __restrict__ W2) {
    __shared__ float sW1[HID], sb1[HID], sW2[HID * 2];
    int t = threadIdx.x;
    if (t < HID)     { sW1[t] = W1[t]; sb1[t] = b1[t]; }   // prologue
    if (t < HID * 2) { sW2[t] = W2[t]; }
    __syncthreads();
    pdl_wait();                                   // g_s1 ready
    pdl_trigger();

    int i = blockIdx.x * blockDim.x + t;
    if (i >= NN) return;
    float dinv = g_dinv[i];
    float s1   = dinv * (g_s1[i] + g_p[i]);
    float a = 0.f, b = 0.f;
#pragma unroll
    for (int j = 0; j < HID; ++j) {
        float h = fmaxf(fmaf(sW1[j], s1, sb1[j]), 0.f);
        a = fmaf(h, sW2[2 * j],     a);
        b = fmaf(h, sW2[2 * j + 1], b);
    }
    g_p2[i] = make_float2(a * dinv, b * dinv);
}

// ---- edge pass 3: acc[c] += p2[r] (global gather, 1 edge/thread — R7) ----
__global__ void __launch_bounds__(256) k_scat2(const int* __restrict__ row,
                                               const int* __restrict__ col) {
    int i = blockIdx.x * blockDim.x + threadIdx.x;
    int r = 0, c = 0;
    if (i < NE) { r = row[i]; c = col[i]; }       // prologue
    pdl_wait();                                   // g_p2 ready
    pdl_trigger();
    if (i < NE) {
        float2 v = *reinterpret_cast<const float2*>(&g_p2[r]);
        atomicAdd(&g_acc[c], v);
    }
}

// ---- final: out = dinv*(acc+p2) + b2 ; reset scratch ----
__global__ void __launch_bounds__(256) k_final(float* __restrict__ out,
                                               const float* __restrict__ b2) {
    int i = blockIdx.x * blockDim.x + threadIdx.x;
    float b2x = b2[0], b2y = b2[1];               // prologue
    pdl_wait();                                   // g_acc ready
    pdl_trigger();
    if (i >= NN) return;
    float dinv = g_dinv[i];
    float2 acc = g_acc[i];
    float2 p2  = g_p2[i];
    float2 o;
    o.x = fmaf(dinv, acc.x + p2.x, b2x);
    o.y = fmaf(dinv, acc.y + p2.y, b2y);
    reinterpret_cast<float2*>(out)[i] = o;

    g_deg[i] = 0;
    g_s1[i]  = 0.f;
    g_acc[i] = make_float2(0.f, 0.f);
}

// ---- host ----

static void launch_pdl(const void* fn, int grid, int block, void** args,
                       size_t smem = 0) {
    cudaLaunchConfig_t cfg = {};
    cfg.gridDim  = dim3(grid, 1, 1);
    cfg.blockDim = dim3(block, 1, 1);
    cfg.dynamicSmemBytes = smem;
    cfg.stream   = 0;
    cudaLaunchAttribute attr[1];
    attr[0].id = cudaLaunchAttributeProgrammaticStreamSerialization;
    attr[0].val.programmaticStreamSerializationAllowed = 1;
    cfg.attrs    = attr;
    cfg.numAttrs = 1;
    cudaLaunchKernelExC(&cfg, fn, args);
}

extern "C" void kernel_launch(void* const* d_in, const int* in_sizes, int n_in,
                              void* d_out, int out_size) {
    const float* x   = (const float*)d_in[0];
    const int*   ei  = (const int*)d_in[1];   // [2, NE]
    const float* W1  = (const float*)d_in[2];
    const float* b1  = (const float*)d_in[3];
    const float* W2  = (const float*)d_in[4];
    const float* b2  = (const float*)d_in[5];
    float* out = (float*)d_out;

    const int* row = ei;
    const int* col = ei + NE;

    const size_t SM1 = (size_t)NN * sizeof(float);      // 200000 B

    static bool attr_done = false;
    if (!attr_done) {
        cudaFuncSetAttribute(k_scat1, cudaFuncAttributeMaxDynamicSharedMemorySize, (int)SM1);
        attr_done = true;
    }

    int dev = 0, nsm = 148;
    cudaGetDevice(&dev);
    cudaDeviceGetAttribute(&nsm, cudaDevAttrMultiProcessorCount, dev);

    const int TB = 256;
    const int nodeBlocks = (NN + TB - 1) / TB;
    const int edgeBlocks = (NE + TB - 1) / TB;

    { void* a[] = { (void*)&col };                        launch_pdl((const void*)k_count, edgeBlocks, TB, a); }
    { void* a[] = { (void*)&x };                          launch_pdl((const void*)k_node1, nodeBlocks, TB, a); }
    { void* a[] = { (void*)&row, (void*)&col };           launch_pdl((const void*)k_scat1, nsm, 1024, a, SM1); }
    { void* a[] = { (void*)&W1, (void*)&b1, (void*)&W2 }; launch_pdl((const void*)k_node2, nodeBlocks, TB, a); }
    { void* a[] = { (void*)&row, (void*)&col };           launch_pdl((const void*)k_scat2, edgeBlocks, TB, a); }
    { void* a[] = { (void*)&out, (void*)&b2 };            launch_pdl((const void*)k_final, nodeBlocks, TB, a); }
}

// round 14
// speedup vs baseline: 1.0536x; 1.0536x over previous
#include <cuda_runtime.h>

// GCN_12867722019091 — 2-layer GCN, N=50000, E=800000, HID=64, OUT=2.
// R7 split-PDL chain (proven 32.8us) + ONE change: scat1 gathers p[] from a
// full 195KB smem table. R12/R13's regression was the scalar fill loop
// (~49 dependent 4B LDG->STS @250cyc L2 = ~6us); now float4 + unroll -> ~0.7us.

constexpr int NN  = 50000;
constexpr int NE  = 800000;
constexpr int HID = 64;

__device__ int    g_deg[NN];
__device__ float  g_dinv[NN];
__device__ float  g_p[NN];      // x[n] * dinv[n]
__device__ float  g_s1[NN];     // layer-1 scalar scatter accumulator
__device__ float2 g_p2[NN];     // g[n,:] * dinv[n]
__device__ float2 g_acc[NN];    // layer-2 float2 scatter accumulator

__device__ __forceinline__ void pdl_wait() {
#if __CUDA_ARCH__ >= 900
    asm volatile("griddepcontrol.wait;" ::: "memory");
#endif
}
__device__ __forceinline__ void pdl_trigger() {
#if __CUDA_ARCH__ >= 900
    asm volatile("griddepcontrol.launch_dependents;" ::: "memory");
#endif
}

// ---- edge pass 1: in-degree count (1 edge/thread — proven) ----
__global__ void __launch_bounds__(256) k_count(const int* __restrict__ col) {
    int i = blockIdx.x * blockDim.x + threadIdx.x;
    int c = (i < NE) ? col[i] : 0;               // prologue (independent)
    pdl_wait();                                   // prev replay's reset done
    pdl_trigger();
    if (i < NE) atomicAdd(&g_deg[c], 1);
}

// ---- node pass 1: dinv = rsqrt(deg+1); p = x*dinv ----
__global__ void __launch_bounds__(256) k_node1(const float* __restrict__ x) {
    int i = blockIdx.x * blockDim.x + threadIdx.x;
    float xv = (i < NN) ? x[i] : 0.f;             // prologue
    pdl_wait();                                   // g_deg ready
    pdl_trigger();
    if (i >= NN) return;
    float dinv = rsqrtf((float)(g_deg[i] + 1));
    g_dinv[i] = dinv;
    g_p[i]    = xv * dinv;
}

// ---- edge pass 2: s1[c] += p[r], gather from full smem table ----
__global__ void __launch_bounds__(1024) k_scat1(const int* __restrict__ row,
                                                const int* __restrict__ col) {
    extern __shared__ float sp[];                 // NN floats = 195.3 KB
    pdl_wait();                                   // g_p ready
    pdl_trigger();
    const int t  = threadIdx.x;
    const int nt = gridDim.x * 1024;

    // fill: float4, unrolled -> many independent LDG.128 in flight
    const float4* __restrict__ src = reinterpret_cast<const float4*>(g_p);
    float4* dst = reinterpret_cast<float4*>(sp);
#pragma unroll 8
    for (int i = t; i < NN / 4; i += 1024)        // 12500 float4, ~13 iters
        dst[i] = src[i];
    __syncthreads();

#pragma unroll 4
    for (int i = blockIdx.x * 1024 + t; i < NE; i += nt) {
        int r = row[i];
        int c = col[i];
        atomicAdd(&g_s1[c], sp[r]);
    }
}

// ---- node pass 2: s1 = dinv*(acc+p); h1 = relu(W1*s1+b1); p2 = (h1@W2)*dinv ----
__global__ void __launch_bounds__(256) k_node2(const float* __restrict__ W1,
                                               const float* __restrict__ b1,
                                               const float* __restrict__ W2) {
    __shared__ float sW1[HID], sb1[HID], sW2[HID * 2];
    int t = threadIdx.x;
    if (t < HID)     { sW1[t] = W1[t]; sb1[t] = b1[t]; }   // prologue
    if (t < HID * 2) { sW2[t] = W2[t]; }
    __syncthreads();
    pdl_wait();                                   // g_s1 ready
    pdl_trigger();

    int i = blockIdx.x * blockDim.x + t;
    if (i >= NN) return;
    float dinv = g_dinv[i];
    float s1   = dinv * (g_s1[i] + g_p[i]);
    float a = 0.f, b = 0.f;
#pragma unroll
    for (int j = 0; j < HID; ++j) {
        float h = fmaxf(fmaf(sW1[j], s1, sb1[j]), 0.f);
        a = fmaf(h, sW2[2 * j],     a);
        b = fmaf(h, sW2[2 * j + 1], b);
    }
    g_p2[i] = make_float2(a * dinv, b * dinv);
}

// ---- edge pass 3: acc[c] += p2[r] (plain global gather, 1 edge/thread) ----
__global__ void __launch_bounds__(256) k_scat2(const int* __restrict__ row,
                                               const int* __restrict__ col) {
    int i = blockIdx.x * blockDim.x + threadIdx.x;
    int r = 0, c = 0;
    if (i < NE) { r = row[i]; c = col[i]; }       // prologue
    pdl_wait();                                   // g_p2 ready
    pdl_trigger();
    if (i < NE) {
        float2 v = *reinterpret_cast<const float2*>(&g_p2[r]);
        atomicAdd(&g_acc[c], v);
    }
}

// ---- final: out = dinv*(acc+p2) + b2 ; reset scratch ----
__global__ void __launch_bounds__(256) k_final(float* __restrict__ out,
                                               const float* __restrict__ b2) {
    int i = blockIdx.x * blockDim.x + threadIdx.x;
    float b2x = b2[0], b2y = b2[1];               // prologue
    pdl_wait();                                   // g_acc ready
    pdl_trigger();
    if (i >= NN) return;
    float dinv = g_dinv[i];
    float2 acc = g_acc[i];
    float2 p2  = g_p2[i];
    float2 o;
    o.x = fmaf(dinv, acc.x + p2.x, b2x);
    o.y = fmaf(dinv, acc.y + p2.y, b2y);
    reinterpret_cast<float2*>(out)[i] = o;

    g_deg[i] = 0;
    g_s1[i]  = 0.f;
    g_acc[i] = make_float2(0.f, 0.f);
}

// ---- host ----

static void launch_pdl(const void* fn, int grid, int block, void** args,
                       size_t smem = 0) {
    cudaLaunchConfig_t cfg = {};
    cfg.gridDim  = dim3(grid, 1, 1);
    cfg.blockDim = dim3(block, 1, 1);
    cfg.dynamicSmemBytes = smem;
    cfg.stream   = 0;
    cudaLaunchAttribute attr[1];
    attr[0].id = cudaLaunchAttributeProgrammaticStreamSerialization;
    attr[0].val.programmaticStreamSerializationAllowed = 1;
    cfg.attrs    = attr;
    cfg.numAttrs = 1;
    cudaLaunchKernelExC(&cfg, fn, args);
}

extern "C" void kernel_launch(void* const* d_in, const int* in_sizes, int n_in,
                              void* d_out, int out_size) {
    const float* x   = (const float*)d_in[0];
    const int*   ei  = (const int*)d_in[1];   // [2, NE]
    const float* W1  = (const float*)d_in[2];
    const float* b1  = (const float*)d_in[3];
    const float* W2  = (const float*)d_in[4];
    const float* b2  = (const float*)d_in[5];
    float* out = (float*)d_out;

    const int* row = ei;
    const int* col = ei + NE;

    const size_t SM1 = (size_t)NN * sizeof(float);      // 200000 B
    cudaFuncSetAttribute(k_scat1, cudaFuncAttributeMaxDynamicSharedMemorySize,
                         (int)SM1);

    int dev = 0, nsm = 148;
    cudaGetDevice(&dev);
    cudaDeviceGetAttribute(&nsm, cudaDevAttrMultiProcessorCount, dev);

    const int TB = 256;
    const int nodeBlocks = (NN + TB - 1) / TB;
    const int edgeBlocks = (NE + TB - 1) / TB;

    { void* a[] = { (void*)&col };                        launch_pdl((const void*)k_count, edgeBlocks, TB, a); }
    { void* a[] = { (void*)&x };                          launch_pdl((const void*)k_node1, nodeBlocks, TB, a); }
    { void* a[] = { (void*)&row, (void*)&col };           launch_pdl((const void*)k_scat1, nsm, 1024, a, SM1); }
    { void* a[] = { (void*)&W1, (void*)&b1, (void*)&W2 }; launch_pdl((const void*)k_node2, nodeBlocks, TB, a); }
    { void* a[] = { (void*)&row, (void*)&col };           launch_pdl((const void*)k_scat2, edgeBlocks, TB, a); }
    { void* a[] = { (void*)&out, (void*)&b2 };            launch_pdl((const void*)k_final, nodeBlocks, TB, a); }
}

// round 15
// speedup vs baseline: 1.2064x; 1.1451x over previous
#include <cuda_runtime.h>

// GCN_12867722019091 — 2-layer GCN, N=50000, E=800000, HID=64, OUT=2.
// R7 split-PDL chain (proven 32.8us). R12-R14 smem-gather line is dead
// (gather overlaps RED issue in the plain version; persistent shapes eat
// cross-SM spread as tail). This round: micro-opts only — int4/int2 edge
// loads for fewer index instructions and 2x per-thread MLP on the scatters.

constexpr int NN  = 50000;
constexpr int NE  = 800000;
constexpr int HID = 64;

__device__ int    g_deg[NN];
__device__ float  g_dinv[NN];
__device__ float  g_p[NN];      // x[n] * dinv[n]
__device__ float  g_s1[NN];     // layer-1 scalar scatter accumulator
__device__ float2 g_p2[NN];     // g[n,:] * dinv[n]
__device__ float2 g_acc[NN];    // layer-2 float2 scatter accumulator

__device__ __forceinline__ void pdl_wait() {
#if __CUDA_ARCH__ >= 900
    asm volatile("griddepcontrol.wait;" ::: "memory");
#endif
}
__device__ __forceinline__ void pdl_trigger() {
#if __CUDA_ARCH__ >= 900
    asm volatile("griddepcontrol.launch_dependents;" ::: "memory");
#endif
}

// ---- edge pass 1: in-degree count, 4 edges/thread (int4) ----
__global__ void __launch_bounds__(256) k_count(const int* __restrict__ col) {
    int i = blockIdx.x * blockDim.x + threadIdx.x;      // NE/4 threads
    int4 c = make_int4(0, 0, 0, 0);
    bool ok = (i * 4 < NE);
    if (ok) c = *reinterpret_cast<const int4*>(col + i * 4);   // prologue
    pdl_wait();                                   // prev replay's reset done
    pdl_trigger();
    if (ok) {
        atomicAdd(&g_deg[c.x], 1);
        atomicAdd(&g_deg[c.y], 1);
        atomicAdd(&g_deg[c.z], 1);
        atomicAdd(&g_deg[c.w], 1);
    }
}

// ---- node pass 1: dinv = rsqrt(deg+1); p = x*dinv ----
__global__ void __launch_bounds__(256) k_node1(const float* __restrict__ x) {
    int i = blockIdx.x * blockDim.x + threadIdx.x;
    float xv = (i < NN) ? x[i] : 0.f;             // prologue
    pdl_wait();                                   // g_deg ready
    pdl_trigger();
    if (i >= NN) return;
    float dinv = rsqrtf((float)(g_deg[i] + 1));
    g_dinv[i] = dinv;
    g_p[i]    = xv * dinv;
}

// ---- edge pass 2: s1[c] += p[r], 2 edges/thread (int2) ----
__global__ void __launch_bounds__(256) k_scat1(const int* __restrict__ row,
                                               const int* __restrict__ col) {
    int i = blockIdx.x * blockDim.x + threadIdx.x;      // NE/2 threads
    int2 r = make_int2(0, 0), c = make_int2(0, 0);
    bool ok = (i * 2 < NE);
    if (ok) {                                     // prologue: coalesced int2
        r = *reinterpret_cast<const int2*>(row + i * 2);
        c = *reinterpret_cast<const int2*>(col + i * 2);
    }
    pdl_wait();                                   // g_p ready
    pdl_trigger();
    if (ok) {
        float vx = __ldg(&g_p[r.x]);              // 2 independent chains
        float vy = __ldg(&g_p[r.y]);
        atomicAdd(&g_s1[c.x], vx);
        atomicAdd(&g_s1[c.y], vy);
    }
}

// ---- node pass 2: s1 = dinv*(acc+p); h1 = relu(W1*s1+b1); p2 = (h1@W2)*dinv ----
__global__ void __launch_bounds__(256) k_node2(const float* __restrict__ W1,
                                               const float* __restrict__ b1,
                                               const float* __restrict__ W2) {
    __shared__ float sW1[HID], sb1[HID], sW2[HID * 2];
    int t = threadIdx.x;
    if (t < HID)     { sW1[t] = W1[t]; sb1[t] = b1[t]; }   // prologue
    if (t < HID * 2) { sW2[t] = W2[t]; }
    __syncthreads();
    pdl_wait();                                   // g_s1 ready
    pdl_trigger();

    int i = blockIdx.x * blockDim.x + t;
    if (i >= NN) return;
    float dinv = g_dinv[i];
    float s1   = dinv * (g_s1[i] + g_p[i]);
    float a = 0.f, b = 0.f;
#pragma unroll
    for (int j = 0; j < HID; ++j) {
        float h = fmaxf(fmaf(sW1[j], s1, sb1[j]), 0.f);
        a = fmaf(h, sW2[2 * j],     a);
        b = fmaf(h, sW2[2 * j + 1], b);
    }
    g_p2[i] = make_float2(a * dinv, b * dinv);
}

// ---- edge pass 3: acc[c] += p2[r], 2 edges/thread (int2) ----
__global__ void __launch_bounds__(256) k_scat2(const int* __restrict__ row,
                                               const int* __restrict__ col) {
    int i = blockIdx.x * blockDim.x + threadIdx.x;      // NE/2 threads
    int2 r = make_int2(0, 0), c = make_int2(0, 0);
    bool ok = (i * 2 < NE);
    if (ok) {                                     // prologue
        r = *reinterpret_cast<const int2*>(row + i * 2);
        c = *reinterpret_cast<const int2*>(col + i * 2);
    }
    pdl_wait();                                   // g_p2 ready
    pdl_trigger();
    if (ok) {
        float2 vx = *reinterpret_cast<const float2*>(&g_p2[r.x]);
        float2 vy = *reinterpret_cast<const float2*>(&g_p2[r.y]);
        atomicAdd(&g_acc[c.x], vx);
        atomicAdd(&g_acc[c.y], vy);
    }
}

// ---- final: out = dinv*(acc+p2) + b2 ; reset scratch ----
__global__ void __launch_bounds__(256) k_final(float* __restrict__ out,
                                               const float* __restrict__ b2) {
    int i = blockIdx.x * blockDim.x + threadIdx.x;
    float b2x = b2[0], b2y = b2[1];               // prologue
    pdl_wait();                                   // g_acc ready
    pdl_trigger();
    if (i >= NN) return;
    float dinv = g_dinv[i];
    float2 acc = g_acc[i];
    float2 p2  = g_p2[i];
    float2 o;
    o.x = fmaf(dinv, acc.x + p2.x, b2x);
    o.y = fmaf(dinv, acc.y + p2.y, b2y);
    reinterpret_cast<float2*>(out)[i] = o;

    g_deg[i] = 0;
    g_s1[i]  = 0.f;
    g_acc[i] = make_float2(0.f, 0.f);
}

// ---- host ----

static void launch_pdl(const void* fn, int grid, int block, void** args) {
    cudaLaunchConfig_t cfg = {};
    cfg.gridDim  = dim3(grid, 1, 1);
    cfg.blockDim = dim3(block, 1, 1);
    cfg.stream   = 0;
    cudaLaunchAttribute attr[1];
    attr[0].id = cudaLaunchAttributeProgrammaticStreamSerialization;
    attr[0].val.programmaticStreamSerializationAllowed = 1;
    cfg.attrs    = attr;
    cfg.numAttrs = 1;
    cudaLaunchKernelExC(&cfg, fn, args);
}

extern "C" void kernel_launch(void* const* d_in, const int* in_sizes, int n_in,
                              void* d_out, int out_size) {
    const float* x   = (const float*)d_in[0];
    const int*   ei  = (const int*)d_in[1];   // [2, NE]
    const float* W1  = (const float*)d_in[2];
    const float* b1  = (const float*)d_in[3];
    const float* W2  = (const float*)d_in[4];
    const float* b2  = (const float*)d_in[5];
    float* out = (float*)d_out;

    const int* row = ei;
    const int* col = ei + NE;

    const int TB = 256;
    const int nodeBlocks  = (NN + TB - 1) / TB;
    const int edge4Blocks = (NE / 4 + TB - 1) / TB;   // count: 4 edges/thread
    const int edge2Blocks = (NE / 2 + TB - 1) / TB;   // scats: 2 edges/thread

    { void* a[] = { (void*)&col };                        launch_pdl((const void*)k_count, edge4Blocks, TB, a); }
    { void* a[] = { (void*)&x };                          launch_pdl((const void*)k_node1, nodeBlocks, TB, a); }
    { void* a[] = { (void*)&row, (void*)&col };           launch_pdl((const void*)k_scat1, edge2Blocks, TB, a); }
    { void* a[] = { (void*)&W1, (void*)&b1, (void*)&W2 }; launch_pdl((const void*)k_node2, nodeBlocks, TB, a); }
    { void* a[] = { (void*)&row, (void*)&col };           launch_pdl((const void*)k_scat2, edge2Blocks, TB, a); }
    { void* a[] = { (void*)&out, (void*)&b2 };            launch_pdl((const void*)k_final, nodeBlocks, TB, a); }
}